// round 4
// baseline (speedup 1.0000x reference)
#include <cuda_runtime.h>
#include <cstdio>

// MatchSegmentation: matching = argmax_g S[k,g]; greedy dedup by ce_val.
// All comparisons in log2 units (monotone rescale of reference ce).
// Output written as FLOAT values (harness output dtype is float32 —
// the exact-1.0 rel_err signature of denormal reinterpretation).

#define KK    21          // predicted segments (== out_size)
#define EPSF  1e-6f
#define TILE  32          // pixels per tile (one lane each)
#define KGRP  3           // k's per thread
#define NKG   7           // 21 / 3
#define TPB   (TILE*NKG)  // 224 threads
#define NBLK  296         // 2 CTAs per SM

// Accumulator: [k][g] for g<21 holds S (sum gt*d), [k][21] holds A (sum l1p).
__device__ float g_M[KK][KK + 1];

__global__ void zero_kernel() {
    int t = threadIdx.x;
    if (t < KK * (KK + 1)) ((float*)g_M)[t] = 0.0f;
}

// True if first 64 words all have uint value <= 1 (binary int mask pattern).
// seg is uniform(0,1) float32: bit patterns ~0x3E000000+ — never <= 1.
__device__ __forceinline__ bool looks_like_gt(const void* p) {
    const unsigned* u = (const unsigned*)p;
    bool r = true;
#pragma unroll
    for (int i = 0; i < 64; i++) r = r && (u[i] <= 1u);
    return r;
}

__global__ __launch_bounds__(TPB, 2)
void accum_kernel(const void* __restrict__ bigA, const void* __restrict__ bigB,
                  int N, int GMAX)
{
    const bool a_is_gt = looks_like_gt(bigA);
    const float* __restrict__ seg = (const float*)(a_is_gt ? bigB : bigA);
    const int*   __restrict__ gt  = (const int*)  (a_is_gt ? bigA : bigB);

    __shared__ float s_seg[TILE * KK];  // [pixel_local][k]
    __shared__ float s_gtf[TILE * KK];  // [pixel_local][g]

    const int tid  = threadIdx.x;
    const int lane = tid & 31;   // pixel within tile
    const int kg   = tid >> 5;   // k-group 0..6

    float S[KGRP][KK];
    float A[KGRP];
#pragma unroll
    for (int j = 0; j < KGRP; j++) {
        A[j] = 0.0f;
#pragma unroll
        for (int g = 0; g < KK; g++) S[j][g] = 0.0f;
    }

    const int ntiles = (N + TILE - 1) / TILE;
    for (int t = blockIdx.x; t < ntiles; t += gridDim.x) {
        const int base = t * TILE;
        __syncthreads();
        // Stage 672 floats each from seg and gt, fully coalesced.
        for (int i = tid; i < TILE * KK; i += TPB) {
            long long idx = (long long)base * KK + i;
            s_seg[i] = (idx < (long long)N * KK) ? seg[idx] : 0.5f;
            int g = i >> 5;
            int p = base + (i & 31);
            s_gtf[(i & 31) * KK + g] =
                (p < N && g < GMAX) ? (float)gt[(long long)g * N + p] : 0.0f;
        }
        __syncthreads();

        const int   p  = base + lane;
        const float vm = (p < N) ? 1.0f : 0.0f;

        float gf[KK];
#pragma unroll
        for (int g = 0; g < KK; g++) gf[g] = s_gtf[lane * KK + g];  // stride 21: conflict-free

#pragma unroll
        for (int j = 0; j < KGRP; j++) {
            const int k = kg * KGRP + j;
            float s  = s_seg[lane * KK + k];
            float lp = __log2f(s + EPSF);
            float l1 = __log2f(1.0f - s + EPSF);
            float d  = (lp - l1) * vm;
            A[j] += l1 * vm;
#pragma unroll
            for (int g = 0; g < KK; g++)
                S[j][g] = fmaf(gf[g], d, S[j][g]);
        }
    }

    // Warp reduce (lanes = pixels), then atomic into global accumulator.
#pragma unroll
    for (int j = 0; j < KGRP; j++) {
        const int k = kg * KGRP + j;
#pragma unroll
        for (int g = 0; g < KK; g++) {
            float v = S[j][g];
            v += __shfl_down_sync(0xffffffffu, v, 16);
            v += __shfl_down_sync(0xffffffffu, v, 8);
            v += __shfl_down_sync(0xffffffffu, v, 4);
            v += __shfl_down_sync(0xffffffffu, v, 2);
            v += __shfl_down_sync(0xffffffffu, v, 1);
            if (lane == 0) atomicAdd(&g_M[k][g], v);
        }
        float a = A[j];
        a += __shfl_down_sync(0xffffffffu, a, 16);
        a += __shfl_down_sync(0xffffffffu, a, 8);
        a += __shfl_down_sync(0xffffffffu, a, 4);
        a += __shfl_down_sync(0xffffffffu, a, 2);
        a += __shfl_down_sync(0xffffffffu, a, 1);
        if (lane == 0) atomicAdd(&g_M[k][KK], a);
    }
}

__global__ void finalize_kernel(const int* __restrict__ gpn,
                                float* __restrict__ out, int GMAX)
{
    __shared__ float sM[KK][KK + 1];
    __shared__ int   m[KK];
    __shared__ float val[KK];
    __shared__ int   bestk[KK];

    const int t = threadIdx.x;
    if (t < KK * (KK + 1)) ((float*)sM)[t] = ((const float*)g_M)[t];
    __syncthreads();

    // Robust gt_plane_num read: accept plausible int, then plausible float
    // bit-pattern, else fall back to GMAX.
    int G = GMAX;
    if (gpn != nullptr) {
        int gi = gpn[0];
        if (gi >= 1 && gi <= GMAX) {
            G = gi;
        } else {
            float gfv = __int_as_float(gi);
            if (gfv >= 1.0f && gfv <= (float)GMAX && gfv == floorf(gfv))
                G = (int)gfv;
        }
    }

    // Per-k: matching = argmax_g S (== argmin_g ce; first-occurrence via strict >)
    if (t < KK) {
        int   best = 0;
        float bv   = sM[t][0];
        for (int g = 1; g < G; g++) {
            float v = sM[t][g];
            if (v > bv) { bv = v; best = g; }
        }
        m[t]   = best;
        val[t] = sM[t][KK] + bv;   // A + S_best : larger val == smaller ce_val
    }
    __syncthreads();

    // Greedy dedup (serial, <=21x21 — trivial). Output as FLOAT values.
    if (t == 0) {
        int maxi = 0;
        for (int k = 0; k < KK; k++) if (m[k] > maxi) maxi = m[k];
        maxi += 1;
        for (int g = 0; g < G; g++) {
            float bb = -3.4e38f;
            int   bk = -1;
            for (int k = 0; k < KK; k++)
                if (m[k] == g && val[k] > bb) { bb = val[k]; bk = k; }
            bestk[g] = bk;
        }
        for (int k = 0; k < KK; k++)
            out[k] = (float)((bestk[m[k]] == k) ? m[k] : maxi);
    }
}

extern "C" void kernel_launch(void* const* d_in, const int* in_sizes, int n_in,
                              void* d_out, int out_size)
{
    // Diagnostics (host-side: runs only at call/capture time, not replay).
    printf("[ms-diag] n_in=%d out_size=%d sizes:", n_in, out_size);
    for (int i = 0; i < n_in; i++) printf(" %d", in_sizes[i]);
    printf("\n");
    fflush(stdout);

    // Identify inputs by size, not position.
    int scalar_idx = -1;
    for (int i = 0; i < n_in; i++)
        if (in_sizes[i] == 1) { scalar_idx = i; break; }

    int big[2] = {-1, -1};
    int nb = 0;
    for (int i = 0; i < n_in && nb < 2; i++)
        if (i != scalar_idx) big[nb++] = i;

    const void* A = d_in[big[0]];
    const void* B = d_in[big[1]];
    const int* gpn = (scalar_idx >= 0) ? (const int*)d_in[scalar_idx] : nullptr;

    int bigsize = in_sizes[big[0]];
    int N    = bigsize / KK;
    int GMAX = (N > 0) ? (bigsize / N) : KK;
    if (GMAX > KK) GMAX = KK;
    if (GMAX < 1)  GMAX = 1;

    zero_kernel<<<1, 512>>>();
    accum_kernel<<<NBLK, TPB>>>(A, B, N, GMAX);
    finalize_kernel<<<1, 512>>>(gpn, (float*)d_out, GMAX);
}

// round 5
// speedup vs baseline: 1.2513x; 1.2513x over previous
#include <cuda_runtime.h>
#include <cstdint>
#include <cstdio>

// MatchSegmentation, single fused kernel.
// matching = argmax_g S[k,g] (log2-space CE, monotone rescale); greedy dedup.
// Double-buffered cp.async pipeline; per-CTA partials; last-block finalize.

#define KK   21            // predicted segments (== out_size)
#define EPSF 1e-6f
#define PIX  128           // pixels per tile
#define KGRP 3             // k's per thread
#define NKG  7             // 21/3 k-groups (warps)
#define TPB  (32*NKG)      // 224 threads
#define NBLK 296           // 2 CTAs/SM on 148 SMs
#define ROWW (KK+1)        // 22: [k][g<21]=S, [k][21]=A
#define NENT (KK*ROWW)     // 462

__device__ float g_part[NBLK][NENT];
__device__ int   g_ctr;    // zero-init; last block resets to 0 each run

// gt_instance is int32 0/1; uniform(0,1) float bits are never <= 1.
__device__ __forceinline__ bool looks_like_gt(const void* p) {
    const unsigned* u = (const unsigned*)p;
    bool r = true;
#pragma unroll
    for (int i = 0; i < 64; i++) r = r && (u[i] <= 1u);
    return r;
}

__device__ __forceinline__ void cp16(uint32_t saddr, const void* gaddr) {
    asm volatile("cp.async.cg.shared.global [%0], [%1], 16;"
                 :: "r"(saddr), "l"(gaddr));
}
__device__ __forceinline__ void cp_commit() {
    asm volatile("cp.async.commit_group;");
}
__device__ __forceinline__ void cp_wait0() {
    asm volatile("cp.async.wait_group 0;");
}

__global__ __launch_bounds__(TPB, 2)
void match_kernel(const void* __restrict__ bigA, const void* __restrict__ bigB,
                  const int* __restrict__ gpn, float* __restrict__ out,
                  int N, int GMAX)
{
    const bool a_is_gt = looks_like_gt(bigA);
    const float* __restrict__ seg = (const float*)(a_is_gt ? bigB : bigA);
    const int*   __restrict__ gt  = (const int*)  (a_is_gt ? bigA : bigB);

    __shared__ float s_seg[2][PIX * KK];   // [px][k], 10.5KB each
    __shared__ float s_gt [2][PIX * KK];   // [px][g]
    __shared__ float s_red[NENT];
    __shared__ int   s_last;

    const int tid  = threadIdx.x;
    const int lane = tid & 31;
    const int kg   = tid >> 5;            // 0..6
    const int NK   = N * KK;

    float S[KGRP][KK];
    float A[KGRP];
#pragma unroll
    for (int j = 0; j < KGRP; j++) {
        A[j] = 0.0f;
#pragma unroll
        for (int g = 0; g < KK; g++) S[j][g] = 0.0f;
    }

    const int ntiles = (N + PIX - 1) / PIX;
    int  gpre[KK];
    int  t    = blockIdx.x;
    bool have = (t < ntiles);
    int  buf  = 0;

    // ---- prologue: issue tile t into buffer 0 ----
    if (have) {
        const int tilebase = t * (PIX * KK);
#pragma unroll
        for (int j = 0; j < 3; j++) {
            const int i    = tid + j * TPB;        // float4 slot 0..671
            const int fidx = tilebase + i * 4;
            if (fidx + 3 < NK) {
                cp16((uint32_t)__cvta_generic_to_shared(&s_seg[0][i * 4]),
                     seg + fidx);
            } else {
#pragma unroll
                for (int w = 0; w < 4; w++)
                    s_seg[0][i * 4 + w] = (fidx + w < NK) ? seg[fidx + w] : 0.0f;
            }
        }
        cp_commit();
        if (tid < PIX) {
            const int p = t * PIX + tid;
#pragma unroll
            for (int g = 0; g < KK; g++)
                gpre[g] = (p < N && g < GMAX) ? gt[g * N + p] : 0;
        }
    }

    // ---- main pipelined loop ----
    while (have) {
        const int  tn     = t + gridDim.x;
        const bool have_n = (tn < ntiles);

        cp_wait0();                               // seg[t] resident in s_seg[buf]
        if (tid < PIX) {
            const int b = tid * KK;
#pragma unroll
            for (int g = 0; g < KK; g++)
                s_gt[buf][b + g] = (float)gpre[g]; // stride-21 STS: conflict-free
        }
        __syncthreads();

        if (have_n) {                             // issue next tile into 1-buf
            const int tilebase = tn * (PIX * KK);
#pragma unroll
            for (int j = 0; j < 3; j++) {
                const int i    = tid + j * TPB;
                const int fidx = tilebase + i * 4;
                if (fidx + 3 < NK) {
                    cp16((uint32_t)__cvta_generic_to_shared(&s_seg[buf ^ 1][i * 4]),
                         seg + fidx);
                } else {
#pragma unroll
                    for (int w = 0; w < 4; w++)
                        s_seg[buf ^ 1][i * 4 + w] =
                            (fidx + w < NK) ? seg[fidx + w] : 0.0f;
                }
            }
            cp_commit();
            if (tid < PIX) {
                const int p = tn * PIX + tid;
#pragma unroll
                for (int g = 0; g < KK; g++)
                    gpre[g] = (p < N && g < GMAX) ? gt[g * N + p] : 0;
            }
        }

        // compute on buffer `buf` (4 pixel sub-tiles per lane)
#pragma unroll
        for (int q = 0; q < 4; q++) {
            const int px = q * 32 + lane;
            const int pb = px * KK;
            float gf[KK];
#pragma unroll
            for (int g = 0; g < KK; g++) gf[g] = s_gt[buf][pb + g];
#pragma unroll
            for (int j = 0; j < KGRP; j++) {
                const int   k  = kg * KGRP + j;
                const float s  = s_seg[buf][pb + k];
                const float lp = __log2f(s + EPSF);
                const float l1 = __log2f(1.0f - s + EPSF);
                const float d  = lp - l1;
                A[j] += l1;
#pragma unroll
                for (int g = 0; g < KK; g++)
                    S[j][g] = fmaf(gf[g], d, S[j][g]);
            }
        }

        buf ^= 1;
        t    = tn;
        have = have_n;
    }

    // ---- per-CTA warp reduction (lanes = pixels) -> deterministic partials ----
#pragma unroll
    for (int j = 0; j < KGRP; j++) {
        const int k = kg * KGRP + j;
#pragma unroll
        for (int g = 0; g < KK; g++) {
            float v = S[j][g];
            v += __shfl_down_sync(0xffffffffu, v, 16);
            v += __shfl_down_sync(0xffffffffu, v, 8);
            v += __shfl_down_sync(0xffffffffu, v, 4);
            v += __shfl_down_sync(0xffffffffu, v, 2);
            v += __shfl_down_sync(0xffffffffu, v, 1);
            if (lane == 0) g_part[blockIdx.x][k * ROWW + g] = v;
        }
        float a = A[j];
        a += __shfl_down_sync(0xffffffffu, a, 16);
        a += __shfl_down_sync(0xffffffffu, a, 8);
        a += __shfl_down_sync(0xffffffffu, a, 4);
        a += __shfl_down_sync(0xffffffffu, a, 2);
        a += __shfl_down_sync(0xffffffffu, a, 1);
        if (lane == 0) g_part[blockIdx.x][k * ROWW + KK] = a;
    }

    __threadfence();
    __syncthreads();
    if (tid == 0)
        s_last = (atomicAdd(&g_ctr, 1) == (int)gridDim.x - 1) ? 1 : 0;
    __syncthreads();
    if (!s_last) return;
    __threadfence();   // acquire: all other CTAs' partials visible

    // ---- last CTA: reduce partials (8-way split over CTA axis for MLP) ----
    for (int e = tid; e < NENT; e += TPB) s_red[e] = 0.0f;
    __syncthreads();
    {
        const int nc     = (int)gridDim.x;
        const int chunk  = (nc + 7) / 8;
        for (int idx = tid; idx < NENT * 8; idx += TPB) {
            const int e  = idx >> 3;
            const int c0 = (idx & 7) * chunk;
            int c1 = c0 + chunk; if (c1 > nc) c1 = nc;
            float v = 0.0f;
            for (int c = c0; c < c1; c++) v += g_part[c][e];
            atomicAdd(&s_red[e], v);
        }
    }
    __syncthreads();

    // gt_plane_num (robust read: int, else float bits, else GMAX)
    int G = GMAX;
    if (gpn != nullptr) {
        const int gi = gpn[0];
        if (gi >= 1 && gi <= GMAX) G = gi;
        else {
            const float gfv = __int_as_float(gi);
            if (gfv >= 1.0f && gfv <= (float)GMAX && gfv == floorf(gfv))
                G = (int)gfv;
        }
    }

    __shared__ int   m[KK];
    __shared__ float val[KK];
    __shared__ int   bestk[KK];

    // matching = argmax_g S (first occurrence via strict >)
    if (tid < KK) {
        int   best = 0;
        float bv   = s_red[tid * ROWW + 0];
        for (int g = 1; g < G; g++) {
            const float v = s_red[tid * ROWW + g];
            if (v > bv) { bv = v; best = g; }
        }
        m[tid]   = best;
        val[tid] = s_red[tid * ROWW + KK] + bv;  // larger == smaller ce_val
    }
    __syncthreads();

    if (tid == 0) {
        int maxi = 0;
        for (int k = 0; k < KK; k++) if (m[k] > maxi) maxi = m[k];
        maxi += 1;
        for (int g = 0; g < G; g++) {
            float bb = -3.4e38f;
            int   bk = -1;
            for (int k = 0; k < KK; k++)
                if (m[k] == g && val[k] > bb) { bb = val[k]; bk = k; }
            bestk[g] = bk;
        }
        for (int k = 0; k < KK; k++)
            out[k] = (float)((bestk[m[k]] == k) ? m[k] : maxi);
        g_ctr = 0;   // reset for next graph replay
    }
}

extern "C" void kernel_launch(void* const* d_in, const int* in_sizes, int n_in,
                              void* d_out, int out_size)
{
    // Identify inputs by size: scalar = gt_plane_num; two big = seg/gt
    // (disambiguated on-device by bit pattern).
    int scalar_idx = -1;
    for (int i = 0; i < n_in; i++)
        if (in_sizes[i] == 1) { scalar_idx = i; break; }

    int big[2] = {-1, -1};
    int nb = 0;
    for (int i = 0; i < n_in && nb < 2; i++)
        if (i != scalar_idx) big[nb++] = i;

    const void* A   = d_in[big[0]];
    const void* B   = d_in[big[1]];
    const int*  gpn = (scalar_idx >= 0) ? (const int*)d_in[scalar_idx] : nullptr;

    const int bigsize = in_sizes[big[0]];
    int N    = bigsize / KK;
    int GMAX = (N > 0) ? (bigsize / N) : KK;
    if (GMAX > KK) GMAX = KK;
    if (GMAX < 1)  GMAX = 1;

    match_kernel<<<NBLK, TPB>>>(A, B, gpn, (float*)d_out, N, GMAX);
}

// round 6
// speedup vs baseline: 1.6547x; 1.3224x over previous
#include <cuda_runtime.h>
#include <cstdint>

// MatchSegmentation, single fused kernel, register-lean inner loop.
// matching = argmax_g S[k,g] (log2-space CE, monotone rescale); greedy dedup.
// cp.async double-buffered; gt staged as int [g][px], I2F at use (alu pipe);
// per-warp reduce -> atomicAdd(462 floats); last CTA finalizes.

#define KK   21            // predicted segments (== out_size)
#define EPSF 1e-6f
#define PIX  128           // pixels per tile
#define TPB  224           // 7 warps: warp w owns k in {3w, 3w+1, 3w+2}
#define NBLK 296           // 2 CTAs/SM on 148 SMs
#define ROWW (KK+1)        // 22: [k][g<21]=S, [k][21]=A
#define NENT (KK*ROWW)     // 462

__device__ float g_acc[NENT];   // zero at load; last CTA re-zeros each run
__device__ int   g_ctr;

// gt_instance is int32 0/1; uniform(0,1) float bits are never <= 1.
__device__ __forceinline__ bool looks_like_gt(const void* p) {
    const unsigned* u = (const unsigned*)p;
    bool r = true;
#pragma unroll
    for (int i = 0; i < 64; i++) r = r && (u[i] <= 1u);
    return r;
}

__device__ __forceinline__ void cp16(void* sdst, const void* gsrc) {
    uint32_t sa = (uint32_t)__cvta_generic_to_shared(sdst);
    asm volatile("cp.async.cg.shared.global [%0], [%1], 16;" :: "r"(sa), "l"(gsrc));
}
__device__ __forceinline__ void cp_commit() { asm volatile("cp.async.commit_group;"); }
__device__ __forceinline__ void cp_wait0()  { asm volatile("cp.async.wait_group 0;"); }

__device__ __forceinline__ float wred(float v) {
    v += __shfl_down_sync(0xffffffffu, v, 16);
    v += __shfl_down_sync(0xffffffffu, v, 8);
    v += __shfl_down_sync(0xffffffffu, v, 4);
    v += __shfl_down_sync(0xffffffffu, v, 2);
    v += __shfl_down_sync(0xffffffffu, v, 1);
    return v;
}

__global__ __launch_bounds__(TPB, 2)
void match_kernel(const void* __restrict__ bigA, const void* __restrict__ bigB,
                  const int* __restrict__ gpn, float* __restrict__ out,
                  int N, int GMAX)
{
    const bool a_is_gt = looks_like_gt(bigA);
    const float* __restrict__ seg = (const float*)(a_is_gt ? bigB : bigA);
    const int*   __restrict__ gt  = (const int*)  (a_is_gt ? bigA : bigB);

    __shared__ float s_seg[2][PIX * KK];  // [px][k]   10.5KB each
    __shared__ int   s_gti[2][KK * PIX];  // [g][px]   10.5KB each
    __shared__ float s_red[NENT];
    __shared__ int   s_last;

    const int tid  = threadIdx.x;
    const int lane = tid & 31;
    const int kg   = tid >> 5;            // 0..6
    const int k0   = kg * 3;
    const long long NKll = (long long)N * KK;
    const bool alignedN = ((N & 3) == 0);

    float S0[KK], S1[KK], S2[KK];
    float A0 = 0.f, A1 = 0.f, A2 = 0.f;
#pragma unroll
    for (int g = 0; g < KK; g++) { S0[g] = 0.f; S1[g] = 0.f; S2[g] = 0.f; }

    // rows g >= GMAX stay zero forever (loaders only touch g < GMAX)
    if (GMAX < KK) {
        for (int i = tid; i < (KK - GMAX) * PIX; i += TPB) {
            int g = GMAX + i / PIX, c = i % PIX;
            s_gti[0][g * PIX + c] = 0;
            s_gti[1][g * PIX + c] = 0;
        }
    }

    const int ntiles = (N + PIX - 1) / PIX;

    auto load_tile = [&](int tt, int b) {
        const int       base = tt * PIX;
        const long long tb   = (long long)tt * (PIX * KK);
        if (alignedN && base + PIX <= N) {
#pragma unroll
            for (int j = 0; j < 3; j++) {          // 672 float4 slots of seg
                const int i = tid + j * TPB;
                cp16(&s_seg[b][i * 4], seg + tb + i * 4);
            }
#pragma unroll
            for (int j = 0; j < 3; j++) {          // GMAX*32 float4 slots of gt
                const int s = tid + j * TPB;
                if (s < GMAX * 32) {
                    const int g = s >> 5, c = s & 31;
                    cp16(&s_gti[b][g * PIX + c * 4],
                         gt + (long long)g * N + base + c * 4);
                }
            }
        } else {   // generic tail / misaligned fallback
            for (int i = tid; i < PIX * KK; i += TPB) {
                const long long idx = tb + i;
                s_seg[b][i] = (idx < NKll) ? seg[idx] : 0.5f;  // pad: d=0, A const
            }
            for (int s = tid; s < GMAX * PIX; s += TPB) {
                const int g = s / PIX, c = s % PIX, p = base + c;
                s_gti[b][g * PIX + c] = (p < N) ? gt[(long long)g * N + p] : 0;
            }
        }
        cp_commit();
    };

    int  t    = blockIdx.x;
    bool have = (t < ntiles);
    int  buf  = 0;
    if (have) load_tile(t, 0);

    while (have) {
        const int  tn     = t + gridDim.x;
        const bool have_n = (tn < ntiles);

        cp_wait0();
        __syncthreads();                  // tile resident; prev compute done
        if (have_n) load_tile(tn, buf ^ 1);

#pragma unroll
        for (int q = 0; q < 4; q++) {
            const int pb = (q * 32 + lane) * KK;
            float d0, d1, d2;
            {
                const float s  = s_seg[buf][pb + k0];
                const float l1 = __log2f(1.0f - s + EPSF);
                d0 = __log2f(s + EPSF) - l1;  A0 += l1;
            }
            {
                const float s  = s_seg[buf][pb + k0 + 1];
                const float l1 = __log2f(1.0f - s + EPSF);
                d1 = __log2f(s + EPSF) - l1;  A1 += l1;
            }
            {
                const float s  = s_seg[buf][pb + k0 + 2];
                const float l1 = __log2f(1.0f - s + EPSF);
                d2 = __log2f(s + EPSF) - l1;  A2 += l1;
            }
            const int px = q * 32 + lane;
#pragma unroll
            for (int g = 0; g < KK; g++) {
                const float gv = __int2float_rn(s_gti[buf][g * PIX + px]);
                S0[g] = fmaf(gv, d0, S0[g]);
                S1[g] = fmaf(gv, d1, S1[g]);
                S2[g] = fmaf(gv, d2, S2[g]);
            }
        }

        buf ^= 1;
        t    = tn;
        have = have_n;
    }

    // ---- warp reduce (lanes = pixels) -> atomic accumulate ----
#pragma unroll
    for (int g = 0; g < KK; g++) {
        float v0 = wred(S0[g]), v1 = wred(S1[g]), v2 = wred(S2[g]);
        if (lane == 0) {
            atomicAdd(&g_acc[(k0    ) * ROWW + g], v0);
            atomicAdd(&g_acc[(k0 + 1) * ROWW + g], v1);
            atomicAdd(&g_acc[(k0 + 2) * ROWW + g], v2);
        }
    }
    {
        float a0 = wred(A0), a1 = wred(A1), a2 = wred(A2);
        if (lane == 0) {
            atomicAdd(&g_acc[(k0    ) * ROWW + KK], a0);
            atomicAdd(&g_acc[(k0 + 1) * ROWW + KK], a1);
            atomicAdd(&g_acc[(k0 + 2) * ROWW + KK], a2);
        }
    }

    __threadfence();
    __syncthreads();
    if (tid == 0)
        s_last = (atomicAdd(&g_ctr, 1) == (int)gridDim.x - 1) ? 1 : 0;
    __syncthreads();
    if (!s_last) return;
    __threadfence();

    // ---- last CTA: finalize ----
    for (int e = tid; e < NENT; e += TPB) {
        s_red[e] = __ldcg(&g_acc[e]);   // L2 load: fresh post-atomics
        g_acc[e] = 0.0f;                // reset for next replay
    }
    __syncthreads();

    int G = GMAX;
    if (gpn != nullptr) {
        const int gi = gpn[0];
        if (gi >= 1 && gi <= GMAX) G = gi;
        else {
            const float gfv = __int_as_float(gi);
            if (gfv >= 1.0f && gfv <= (float)GMAX && gfv == floorf(gfv))
                G = (int)gfv;
        }
    }

    __shared__ int   m[KK];
    __shared__ float val[KK];
    __shared__ int   bestk[KK];

    if (tid < KK) {   // argmax_g S == argmin_g ce (first occurrence via strict >)
        int   best = 0;
        float bv   = s_red[tid * ROWW + 0];
        for (int g = 1; g < G; g++) {
            const float v = s_red[tid * ROWW + g];
            if (v > bv) { bv = v; best = g; }
        }
        m[tid]   = best;
        val[tid] = s_red[tid * ROWW + KK] + bv;  // larger == smaller ce_val
    }
    __syncthreads();

    if (tid == 0) {
        int maxi = 0;
        for (int k = 0; k < KK; k++) if (m[k] > maxi) maxi = m[k];
        maxi += 1;
        for (int g = 0; g < G; g++) {
            float bb = -3.4e38f;
            int   bk = -1;
            for (int k = 0; k < KK; k++)
                if (m[k] == g && val[k] > bb) { bb = val[k]; bk = k; }
            bestk[g] = bk;
        }
        for (int k = 0; k < KK; k++)
            out[k] = (float)((bestk[m[k]] == k) ? m[k] : maxi);
        g_ctr = 0;
    }
}

extern "C" void kernel_launch(void* const* d_in, const int* in_sizes, int n_in,
                              void* d_out, int out_size)
{
    int scalar_idx = -1;
    for (int i = 0; i < n_in; i++)
        if (in_sizes[i] == 1) { scalar_idx = i; break; }

    int big[2] = {-1, -1};
    int nb = 0;
    for (int i = 0; i < n_in && nb < 2; i++)
        if (i != scalar_idx) big[nb++] = i;

    const void* A   = d_in[big[0]];
    const void* B   = d_in[big[1]];
    const int*  gpn = (scalar_idx >= 0) ? (const int*)d_in[scalar_idx] : nullptr;

    const int bigsize = in_sizes[big[0]];
    int N    = bigsize / KK;
    int GMAX = (N > 0) ? (bigsize / N) : KK;
    if (GMAX > KK) GMAX = KK;
    if (GMAX < 1)  GMAX = 1;

    match_kernel<<<NBLK, TPB>>>(A, B, gpn, (float*)d_out, N, GMAX);
}